// round 1
// baseline (speedup 1.0000x reference)
#include <cuda_runtime.h>

#define B_DIM 8
#define C_DIM 4
#define T_DIM 262144
#define T4 (T_DIM / 4)

// Scratch: per-batch 4x4 distance partial sums (i = y channel, j = x channel)
__device__ float g_partial[B_DIM][16];

__global__ void pit_zero_kernel() {
    int i = threadIdx.x;
    if (i < B_DIM * 16) ((float*)g_partial)[i] = 0.0f;
}

__global__ void __launch_bounds__(256) pit_accum_kernel(
    const float* __restrict__ x, const float* __restrict__ y) {
    const int b = blockIdx.y;
    const float4* __restrict__ x4 =
        (const float4*)(x + (long long)b * C_DIM * T_DIM);
    const float4* __restrict__ y4 =
        (const float4*)(y + (long long)b * C_DIM * T_DIM);

    float acc[16];
#pragma unroll
    for (int k = 0; k < 16; k++) acc[k] = 0.0f;

    const int stride = gridDim.x * blockDim.x;
    for (int idx = blockIdx.x * blockDim.x + threadIdx.x; idx < T4; idx += stride) {
        float4 xv[C_DIM], yv[C_DIM];
#pragma unroll
        for (int c = 0; c < C_DIM; c++) {
            xv[c] = x4[c * T4 + idx];
            yv[c] = y4[c * T4 + idx];
        }
#pragma unroll
        for (int i = 0; i < C_DIM; i++) {
#pragma unroll
            for (int j = 0; j < C_DIM; j++) {
                float d0 = xv[j].x - yv[i].x;
                float d1 = xv[j].y - yv[i].y;
                float d2 = xv[j].z - yv[i].z;
                float d3 = xv[j].w - yv[i].w;
                acc[i * 4 + j] += d0 * d0 + d1 * d1 + d2 * d2 + d3 * d3;
            }
        }
    }

    // Warp reduction for each of the 16 accumulators
#pragma unroll
    for (int k = 0; k < 16; k++) {
#pragma unroll
        for (int off = 16; off > 0; off >>= 1)
            acc[k] += __shfl_down_sync(0xffffffff, acc[k], off);
    }

    __shared__ float s_acc[16];
    if (threadIdx.x < 16) s_acc[threadIdx.x] = 0.0f;
    __syncthreads();
    if ((threadIdx.x & 31) == 0) {
#pragma unroll
        for (int k = 0; k < 16; k++) atomicAdd(&s_acc[k], acc[k]);
    }
    __syncthreads();
    if (threadIdx.x < 16) atomicAdd(&g_partial[b][threadIdx.x], s_acc[threadIdx.x]);
}

__global__ void pit_finalize_kernel(float* __restrict__ out) {
    // single thread: 8 batches x 24 permutations
    const float inv_t = 1.0f / (float)T_DIM;
    float total = 0.0f;
    for (int b = 0; b < B_DIM; b++) {
        float d[16];
#pragma unroll
        for (int k = 0; k < 16; k++) d[k] = g_partial[b][k] * inv_t;
        float best = 3.4e38f;
        for (int p0 = 0; p0 < 4; p0++)
            for (int p1 = 0; p1 < 4; p1++) {
                if (p1 == p0) continue;
                for (int p2 = 0; p2 < 4; p2++) {
                    if (p2 == p0 || p2 == p1) continue;
                    int p3 = 6 - p0 - p1 - p2;
                    // cost = sum_i dists[b, i, perm[i]], row i = y channel
                    float c = d[0 * 4 + p0] + d[1 * 4 + p1] + d[2 * 4 + p2] + d[3 * 4 + p3];
                    best = fminf(best, c);
                }
            }
        total += best;
    }
    out[0] = total;
}

extern "C" void kernel_launch(void* const* d_in, const int* in_sizes, int n_in,
                              void* d_out, int out_size) {
    const float* x = (const float*)d_in[0];
    const float* y = (const float*)d_in[1];
    float* out = (float*)d_out;

    pit_zero_kernel<<<1, 128>>>();
    dim3 grid(64, B_DIM);
    pit_accum_kernel<<<grid, 256>>>(x, y);
    pit_finalize_kernel<<<1, 1>>>(out);
}